// round 10
// baseline (speedup 1.0000x reference)
#include <cuda_runtime.h>
#include <cuda_fp16.h>
#include <cstdint>

// CliffordISTA — Round 9: Pauli/M2(C) fp16 GEMMs (R8) + contention-free grid
// barrier (slot array + release word + nanosleep backoff) + 4-deep smem ring
// with fully-unrolled 4-stage gemm (3-stage prologue, 1 syncthreads/stage).

#define NDIM 512
#define MDIM 256
#define BDIM 64
#define NITER 50
#define STEPF 0.01f
#define KT 64
#define NTHREADS 512
#define GRID 128
#define FWD_SPLIT 8
#define BWD_SPLIT 4
#define KRF 2048   // fwd realified K  (4*NDIM)
#define CCF 1024   // fwd out cols     (4*MDIM)
#define KRB 1024   // bwd realified K
#define CCB 2048   // bwd out cols

#define BUF_BYTES 24576          // per stage: A-op 16K | B-op 8K
#define SMEM_TOTAL (4 * BUF_BYTES)

// ---------------- device globals ----------------
__device__ __half g_Wf[(size_t)CCF * KRF];   // [col][k]  4MB
__device__ __half g_Wb[(size_t)CCB * KRB];   // [col][k]  4MB
__device__ __half g_X[128 * KRF];            // realified x
__device__ __half g_E[128 * KRB];            // realified err
__device__ float g_xs[BDIM * NDIM * 8];      // blade state == output layout
__device__ float g_yr[128 * CCF];            // realified y
__device__ float g_pf[(size_t)FWD_SPLIT * 128 * CCF];
__device__ float g_pb[(size_t)BWD_SPLIT * 128 * CCB];
__device__ unsigned g_slot[GRID * 8];        // arrival slots, 32B apart
__device__ unsigned g_rel;                   // release word

// ---------------- helpers ----------------
__device__ __forceinline__ uint32_t smem_u32(const void* p) {
    uint32_t a;
    asm("{ .reg .u64 t; cvta.to.shared.u64 t, %1; cvt.u32.u64 %0, t; }" : "=r"(a) : "l"(p));
    return a;
}

#define CP_ASYNC16(smem, gptr) \
    asm volatile("cp.async.cg.shared.global [%0], [%1], 16;" :: "r"(smem), "l"(gptr))
#define CP_COMMIT() asm volatile("cp.async.commit_group;" ::: "memory")
#define CP_WAIT2()  asm volatile("cp.async.wait_group 2;" ::: "memory")
#define CP_WAIT1()  asm volatile("cp.async.wait_group 1;" ::: "memory")
#define CP_WAIT0()  asm volatile("cp.async.wait_group 0;" ::: "memory")
#define NSLEEP(n)   asm volatile("nanosleep.u32 %0;" :: "r"((unsigned)(n)))

__device__ __forceinline__ void ldsm4(uint32_t* r, uint32_t addr) {
    asm volatile("ldmatrix.sync.aligned.m8n8.x4.shared.b16 {%0,%1,%2,%3}, [%4];"
                 : "=r"(r[0]), "=r"(r[1]), "=r"(r[2]), "=r"(r[3]) : "r"(addr));
}

__device__ __forceinline__ void mma_fp16(float* c, const uint32_t* a, uint32_t b0, uint32_t b1) {
    asm volatile(
        "mma.sync.aligned.m16n8k16.row.col.f32.f16.f16.f32 "
        "{%0,%1,%2,%3}, {%4,%5,%6,%7}, {%8,%9}, {%0,%1,%2,%3};"
        : "+f"(c[0]), "+f"(c[1]), "+f"(c[2]), "+f"(c[3])
        : "r"(a[0]), "r"(a[1]), "r"(a[2]), "r"(a[3]), "r"(b0), "r"(b1));
}

// M(v)[q][p] for blade vector v[8]  (blades [1,e1,e2,e12,e3,e13,e23,e123])
__device__ __forceinline__ void pauli_entry(const float* v, int q, int p,
                                            float* re, float* im) {
    if (q == 0) {
        if (p == 0) { *re = v[0] + v[4]; *im = v[3] + v[7]; }
        else        { *re = v[1] - v[5]; *im = -v[2] + v[6]; }
    } else {
        if (p == 0) { *re = v[1] + v[5]; *im = v[2] + v[6]; }
        else        { *re = v[0] - v[4]; *im = -v[3] + v[7]; }
    }
}

// ---- grid barrier v2: slot stores + CTA0 aggregation + release word ----
__device__ __forceinline__ void grid_bar(unsigned nb, int cta) {
    __syncthreads();
    const int t = threadIdx.x;
    if (t < 32) {
        if (t == 0) {
            __threadfence();
            asm volatile("st.volatile.global.u32 [%0], %1;"
                         :: "l"(&g_slot[cta * 8]), "r"(nb) : "memory");
        }
        if (cta == 0) {
            bool done = false;
            do {
                unsigned ok = 1;
#pragma unroll
                for (int i = 0; i < 4; i++) {
                    unsigned v;
                    asm volatile("ld.volatile.global.u32 %0, [%1];"
                                 : "=r"(v) : "l"(&g_slot[(t * 4 + i) * 8]));
                    if ((int)(v - nb) < 0) ok = 0;
                }
                done = (__all_sync(0xffffffffu, ok) != 0);
                if (!done) NSLEEP(40);
            } while (!done);
            if (t == 0) {
                __threadfence();
                asm volatile("st.volatile.global.u32 [%0], %1;"
                             :: "l"(&g_rel), "r"(nb) : "memory");
            }
        } else if (t == 0) {
            unsigned v;
            asm volatile("ld.volatile.global.u32 %0, [%1];" : "=r"(v) : "l"(&g_rel));
            while ((int)(v - nb) < 0) {
                NSLEEP(64);
                asm volatile("ld.volatile.global.u32 %0, [%1];" : "=r"(v) : "l"(&g_rel));
            }
            __threadfence();
        }
    }
    __syncthreads();
}

// ---------------- build / init ----------------
__global__ void build_wf(const float* __restrict__ A) {
    size_t idx = (size_t)blockIdx.x * blockDim.x + threadIdx.x;
    if (idx >= (size_t)CCF * KRF) return;
    int col = (int)(idx >> 11), k = (int)(idx & (KRF - 1));
    int m = col >> 2, pp = (col >> 1) & 1, ro = col & 1;
    int n = k >> 2, q = (k >> 1) & 1, ri = k & 1;
    const float* a = A + ((size_t)m * NDIM + n) * 8;
    float re, im;
    pauli_entry(a, q, pp, &re, &im);
    float v = (ri == 0) ? (ro == 0 ? re : im) : (ro == 0 ? -im : re);
    g_Wf[idx] = __float2half(v);
}

__global__ void build_wb(const float* __restrict__ A) {
    size_t idx = (size_t)blockIdx.x * blockDim.x + threadIdx.x;
    if (idx >= (size_t)CCB * KRB) return;
    int col = (int)(idx >> 10), k = (int)(idx & (KRB - 1));
    int n = col >> 2, qp = (col >> 1) & 1, ro = col & 1;
    int m = k >> 2, p = (k >> 1) & 1, ri = k & 1;
    const float* a = A + ((size_t)m * NDIM + n) * 8;
    float re, im;
    pauli_entry(a, qp, p, &re, &im);       // conj(M(A))[q'][p] via signs below
    float v = (ri == 0) ? (ro == 0 ? re : -im) : (ro == 0 ? im : re);
    g_Wb[idx] = __float2half(v);
}

__global__ void build_yr(const float* __restrict__ y) {
    int idx = blockIdx.x * blockDim.x + threadIdx.x;
    if (idx >= 128 * CCF) return;
    int row = idx >> 10, col = idx & (CCF - 1);
    int b = row >> 1, p = row & 1;
    int m = col >> 2, pp = (col >> 1) & 1, ro = col & 1;
    const float* yv = y + ((size_t)b * MDIM + m) * 8;
    float re, im;
    pauli_entry(yv, p, pp, &re, &im);
    g_yr[idx] = ro ? im : re;
}

__global__ void init_all() {
    int idx = blockIdx.x * blockDim.x + threadIdx.x;
    if (idx < BDIM * NDIM * 8) g_xs[idx] = 0.0f;
    if (idx < 128 * KRF) g_X[idx] = __float2half(0.0f);
    if (idx < GRID * 8) g_slot[idx] = 0u;
    if (idx == 0) g_rel = 0u;
}

// ---------------- gemm phase ----------------
// A-op = Xm rows 0..127 [row][k]; B-op = Wm rows c0..c0+63 [col][k]; stride Kdim.
__device__ __forceinline__ void issue_stage(
    uint32_t sb, int buf, int tid, const __half* Xm, const __half* Wm,
    int Kdim, int c0, int kk)
{
    uint32_t base = sb + buf * BUF_BYTES;
#pragma unroll
    for (int r = 0; r < 3; r++) {
        int q = tid + (r << 9);                // 1536 16B chunks per stage
        const __half* gp;
        uint32_t tb;
        int row, cc;
        if (q < 1024) {                        // A: 128 rows x 8 chunks
            row = q >> 3; cc = q & 7;
            gp = Xm + (size_t)row * Kdim + kk + cc * 8;
            tb = base;
        } else {                               // B: 64 rows x 8 chunks
            int q2 = q - 1024;
            row = q2 >> 3; cc = q2 & 7;
            gp = Wm + (size_t)(c0 + row) * Kdim + kk + cc * 8;
            tb = base + 16384;
        }
        uint32_t off = (uint32_t)((row << 7) | ((cc ^ (row & 7)) << 4));
        CP_ASYNC16(tb + off, gp);
    }
    CP_COMMIT();
}

struct WarpCtx {
    int wm, wn, lrow, lhalf, lsw;
};

__device__ __forceinline__ void compute_stage(
    uint32_t bufb, const WarpCtx& w, float acc[2][2][4])
{
#pragma unroll
    for (int kk = 0; kk < 4; kk++) {
        uint32_t ksel = (uint32_t)((((kk << 1) | w.lhalf) ^ w.lsw) << 4);
        uint32_t ah[2][4], bb[4];
#pragma unroll
        for (int am = 0; am < 2; am++) {
            uint32_t rb = (uint32_t)((w.wm * 32 + am * 16 + w.lrow) << 7) + ksel;
            ldsm4(ah[am], bufb + rb);
        }
        {
            uint32_t rb = (uint32_t)((w.wn * 16 + w.lrow) << 7) + ksel;
            ldsm4(bb, bufb + 16384u + rb);
        }
#pragma unroll
        for (int am = 0; am < 2; am++)
#pragma unroll
            for (int sel = 0; sel < 2; sel++)
                mma_fp16(acc[am][sel], ah[am], bb[sel], bb[sel + 2]);
    }
}

// nst == 4 for both gemms (kchunk 256, KT 64): fully unrolled, 4-buffer ring.
__device__ void gemm_phase(uint32_t sb, const __half* Xm, const __half* Wm,
                           float* part, int Kdim, int Cc, int c0, int ks)
{
    const int tid = threadIdx.x;
    const int k0 = ks * 256;

    const int warp = tid >> 5, lane = tid & 31;
    WarpCtx w;
    w.wm = warp >> 2;
    w.wn = warp & 3;
    w.lrow = lane & 15;
    w.lhalf = lane >> 4;
    w.lsw = w.lrow & 7;

    float acc[2][2][4];
#pragma unroll
    for (int am = 0; am < 2; am++)
#pragma unroll
        for (int sel = 0; sel < 2; sel++)
#pragma unroll
            for (int v = 0; v < 4; v++) acc[am][sel][v] = 0.0f;

    // deep prologue: 3 stages in flight before first wait
    issue_stage(sb, 0, tid, Xm, Wm, Kdim, c0, k0);
    issue_stage(sb, 1, tid, Xm, Wm, Kdim, c0, k0 + 64);
    issue_stage(sb, 2, tid, Xm, Wm, Kdim, c0, k0 + 128);

    // stage 0 (issue stage 3 after the sync: all warps are past any prior use)
    CP_WAIT2();
    __syncthreads();
    issue_stage(sb, 3, tid, Xm, Wm, Kdim, c0, k0 + 192);
    compute_stage(sb + 0 * BUF_BYTES, w, acc);
    // stage 1
    CP_WAIT2();
    __syncthreads();
    compute_stage(sb + 1 * BUF_BYTES, w, acc);
    // stage 2
    CP_WAIT1();
    __syncthreads();
    compute_stage(sb + 2 * BUF_BYTES, w, acc);
    // stage 3
    CP_WAIT0();
    __syncthreads();
    compute_stage(sb + 3 * BUF_BYTES, w, acc);

    const int qrow = lane >> 2, qcol2 = (lane & 3) << 1;
    float* po = part + (size_t)ks * 128 * Cc;
#pragma unroll
    for (int am = 0; am < 2; am++)
#pragma unroll
        for (int sel = 0; sel < 2; sel++) {
            int row = w.wm * 32 + am * 16 + qrow;
            int col = c0 + w.wn * 16 + sel * 8 + qcol2;
            *reinterpret_cast<float2*>(&po[(size_t)row * Cc + col]) =
                make_float2(acc[am][sel][0], acc[am][sel][1]);
            *reinterpret_cast<float2*>(&po[(size_t)(row + 8) * Cc + col]) =
                make_float2(acc[am][sel][2], acc[am][sel][3]);
        }
}

// ---------------- persistent kernel ----------------
__global__ __launch_bounds__(NTHREADS, 1) void ista_persist(float* __restrict__ out) {
    extern __shared__ char smem[];
    uint32_t sb = smem_u32(smem);
    const int cta = blockIdx.x;
    const int t = threadIdx.x;
    unsigned nb = 0;

    for (int it = 0; it < NITER; it++) {
        // ---- fwd: pf[ks] = X(128x2048) @ Wf-tile ----
        gemm_phase(sb, g_X, g_Wf, g_pf, KRF, CCF, (cta & 15) * 64, cta >> 4);
        grid_bar(++nb, cta);

        // ---- err: E = sum(pf) - yr, fp16 (128x1024, coalesced) ----
#pragma unroll
        for (int i = 0; i < 2; i++) {
            int idx = cta * NTHREADS + t + i * (GRID * NTHREADS);
            float s = 0.0f;
#pragma unroll
            for (int p = 0; p < FWD_SPLIT; p++)
                s += g_pf[(size_t)p * 128 * CCF + idx];
            g_E[idx] = __float2half(s - g_yr[idx]);
        }
        grid_bar(++nb, cta);

        // ---- bwd: pb[ks] = E(128x1024) @ Wb-tile ----
        gemm_phase(sb, g_E, g_Wb, g_pb, KRB, CCB, (cta >> 2) * 64, cta & 3);
        grid_bar(++nb, cta);

        // ---- upd: matrix->blade, shrink, blade->matrix ----
        {
            int idx = cta * NTHREADS + t;
            if (idx < BDIM * NDIM) {
                int b = idx >> 9, n = idx & (NDIM - 1);
                size_t base0 = (size_t)(2 * b) * CCB + 4 * n;
                size_t base1 = base0 + CCB;
                float4 G0 = make_float4(0.f, 0.f, 0.f, 0.f);
                float4 G1 = make_float4(0.f, 0.f, 0.f, 0.f);
#pragma unroll
                for (int p = 0; p < BWD_SPLIT; p++) {
                    float4 a = *reinterpret_cast<const float4*>(
                        &g_pb[(size_t)p * 128 * CCB + base0]);
                    float4 c = *reinterpret_cast<const float4*>(
                        &g_pb[(size_t)p * 128 * CCB + base1]);
                    G0.x += a.x; G0.y += a.y; G0.z += a.z; G0.w += a.w;
                    G1.x += c.x; G1.y += c.y; G1.z += c.z; G1.w += c.w;
                }
                float g[8];
                g[0] = 0.5f * (G0.x + G1.z);
                g[4] = 0.5f * (G0.x - G1.z);
                g[3] = 0.5f * (G0.y - G1.w);
                g[7] = 0.5f * (G0.y + G1.w);
                g[1] = 0.5f * (G0.z + G1.x);
                g[5] = 0.5f * (G1.x - G0.z);
                g[2] = 0.5f * (G1.y - G0.w);
                g[6] = 0.5f * (G0.w + G1.y);

                float* xs = g_xs + (size_t)idx * 8;
                float x[8];
#pragma unroll
                for (int i = 0; i < 8; i++) {
                    float xv = xs[i] - STEPF * g[i];
                    float thr = (i == 0) ? 0.0f : ((i == 7) ? 0.002f : 0.001f);
                    float a = fabsf(xv) - thr;
                    x[i] = (a > 0.0f) ? copysignf(a, xv) : 0.0f;
                    xs[i] = x[i];
                }
                __half2* X0 = reinterpret_cast<__half2*>(
                    &g_X[(size_t)(2 * b) * KRF + 4 * n]);
                __half2* X1 = reinterpret_cast<__half2*>(
                    &g_X[(size_t)(2 * b + 1) * KRF + 4 * n]);
                X0[0] = __floats2half2_rn(x[0] + x[4], x[3] + x[7]);
                X0[1] = __floats2half2_rn(x[1] - x[5], -x[2] + x[6]);
                X1[0] = __floats2half2_rn(x[1] + x[5], x[2] + x[6]);
                X1[1] = __floats2half2_rn(x[0] - x[4], -x[3] + x[7]);
            }
        }
        grid_bar(++nb, cta);
    }

    // ---- out = blade state (already output layout) ----
    {
        int idx = cta * NTHREADS + t;
        reinterpret_cast<float4*>(out)[idx] =
            reinterpret_cast<const float4*>(g_xs)[idx];
    }
}

// ---------------- host ----------------
extern "C" void kernel_launch(void* const* d_in, const int* in_sizes, int n_in,
                              void* d_out, int out_size)
{
    const float* y = (const float*)d_in[0];
    const float* A = (const float*)d_in[1];
    if (n_in >= 2 && in_sizes[0] > in_sizes[1]) {
        const float* t = y; y = A; A = t;
    }

    cudaFuncSetAttribute(ista_persist, cudaFuncAttributeMaxDynamicSharedMemorySize, SMEM_TOTAL);

    build_wf<<<(int)(((size_t)CCF * KRF + 255) / 256), 256>>>(A);
    build_wb<<<(int)(((size_t)CCB * KRB + 255) / 256), 256>>>(A);
    build_yr<<<(128 * CCF + 255) / 256, 256>>>(y);
    init_all<<<(128 * KRF + 255) / 256, 256>>>();

    ista_persist<<<GRID, NTHREADS, SMEM_TOTAL>>>((float*)d_out);
}

// round 11
// speedup vs baseline: 1.2590x; 1.2590x over previous
#include <cuda_runtime.h>
#include <cuda_fp16.h>
#include <cstdint>

// CliffordISTA — Round 10: R8 base (Pauli/M2(C) fp16 GEMMs, atomic grid barrier)
// + bwd GEMM restructured to full-K per CTA with FUSED upd/shrink epilogue.
// 3 grid barriers per iteration instead of 4; pb partials eliminated.

#define NDIM 512
#define MDIM 256
#define BDIM 64
#define NITER 50
#define STEPF 0.01f
#define KT 64
#define NTHREADS 512
#define GRID 128
#define FWD_SPLIT 8
#define KRF 2048   // fwd realified K  (4*NDIM)
#define CCF 1024   // fwd out cols     (4*MDIM)
#define KRB 1024   // bwd realified K
#define CCB 2048   // bwd out cols

#define BUF_BYTES 24576          // per stage: A-op 16K | B-op 8K (bwd uses 2K of B)
#define SMEM_TOTAL (2 * BUF_BYTES)

// ---------------- device globals ----------------
__device__ __half g_Wf[(size_t)CCF * KRF];   // [col][k]  4MB
__device__ __half g_Wb[(size_t)CCB * KRB];   // [col][k]  4MB
__device__ __half g_X[128 * KRF];            // realified x
__device__ __half g_E[128 * KRB];            // realified err
__device__ float g_xs[BDIM * NDIM * 8];      // blade state == output layout
__device__ float g_yr[128 * CCF];            // realified y
__device__ float g_pf[(size_t)FWD_SPLIT * 128 * CCF];
__device__ unsigned g_sub[8 * 32];           // barrier sub-counters (R8 proven)
__device__ unsigned g_root;

// ---------------- helpers ----------------
__device__ __forceinline__ uint32_t smem_u32(const void* p) {
    uint32_t a;
    asm("{ .reg .u64 t; cvta.to.shared.u64 t, %1; cvt.u32.u64 %0, t; }" : "=r"(a) : "l"(p));
    return a;
}

#define CP_ASYNC16(smem, gptr) \
    asm volatile("cp.async.cg.shared.global [%0], [%1], 16;" :: "r"(smem), "l"(gptr))
#define CP_COMMIT() asm volatile("cp.async.commit_group;" ::: "memory")
#define CP_WAIT1()  asm volatile("cp.async.wait_group 1;" ::: "memory")
#define CP_WAIT0()  asm volatile("cp.async.wait_group 0;" ::: "memory")

__device__ __forceinline__ void ldsm4(uint32_t* r, uint32_t addr) {
    asm volatile("ldmatrix.sync.aligned.m8n8.x4.shared.b16 {%0,%1,%2,%3}, [%4];"
                 : "=r"(r[0]), "=r"(r[1]), "=r"(r[2]), "=r"(r[3]) : "r"(addr));
}

__device__ __forceinline__ void mma_fp16(float* c, const uint32_t* a, uint32_t b0, uint32_t b1) {
    asm volatile(
        "mma.sync.aligned.m16n8k16.row.col.f32.f16.f16.f32 "
        "{%0,%1,%2,%3}, {%4,%5,%6,%7}, {%8,%9}, {%0,%1,%2,%3};"
        : "+f"(c[0]), "+f"(c[1]), "+f"(c[2]), "+f"(c[3])
        : "r"(a[0]), "r"(a[1]), "r"(a[2]), "r"(a[3]), "r"(b0), "r"(b1));
}

// M(v)[q][p] for blade vector v[8]  (blades [1,e1,e2,e12,e3,e13,e23,e123])
__device__ __forceinline__ void pauli_entry(const float* v, int q, int p,
                                            float* re, float* im) {
    if (q == 0) {
        if (p == 0) { *re = v[0] + v[4]; *im = v[3] + v[7]; }
        else        { *re = v[1] - v[5]; *im = -v[2] + v[6]; }
    } else {
        if (p == 0) { *re = v[1] + v[5]; *im = v[2] + v[6]; }
        else        { *re = v[0] - v[4]; *im = -v[3] + v[7]; }
    }
}

// R8's proven grid barrier: 8-way sub-counters -> root, monotonic
__device__ __forceinline__ void grid_bar(unsigned nb, int cta) {
    __syncthreads();
    if (threadIdx.x == 0) {
        __threadfence();
        unsigned prev = atomicAdd(&g_sub[(cta & 7) * 32], 1u);
        if (prev + 1u == 16u * nb)
            atomicAdd(&g_root, 1u);
        unsigned target = 8u * nb, v;
        do {
            asm volatile("ld.volatile.global.u32 %0, [%1];" : "=r"(v) : "l"(&g_root));
        } while ((int)(v - target) < 0);
        __threadfence();
    }
    __syncthreads();
}

// ---------------- build / init ----------------
__global__ void build_wf(const float* __restrict__ A) {
    size_t idx = (size_t)blockIdx.x * blockDim.x + threadIdx.x;
    if (idx >= (size_t)CCF * KRF) return;
    int col = (int)(idx >> 11), k = (int)(idx & (KRF - 1));
    int m = col >> 2, pp = (col >> 1) & 1, ro = col & 1;
    int n = k >> 2, q = (k >> 1) & 1, ri = k & 1;
    const float* a = A + ((size_t)m * NDIM + n) * 8;
    float re, im;
    pauli_entry(a, q, pp, &re, &im);
    float v = (ri == 0) ? (ro == 0 ? re : im) : (ro == 0 ? -im : re);
    g_Wf[idx] = __float2half(v);
}

__global__ void build_wb(const float* __restrict__ A) {
    size_t idx = (size_t)blockIdx.x * blockDim.x + threadIdx.x;
    if (idx >= (size_t)CCB * KRB) return;
    int col = (int)(idx >> 10), k = (int)(idx & (KRB - 1));
    int n = col >> 2, qp = (col >> 1) & 1, ro = col & 1;
    int m = k >> 2, p = (k >> 1) & 1, ri = k & 1;
    const float* a = A + ((size_t)m * NDIM + n) * 8;
    float re, im;
    pauli_entry(a, qp, p, &re, &im);       // conj applied via signs below
    float v = (ri == 0) ? (ro == 0 ? re : -im) : (ro == 0 ? im : re);
    g_Wb[idx] = __float2half(v);
}

__global__ void build_yr(const float* __restrict__ y) {
    int idx = blockIdx.x * blockDim.x + threadIdx.x;
    if (idx >= 128 * CCF) return;
    int row = idx >> 10, col = idx & (CCF - 1);
    int b = row >> 1, p = row & 1;
    int m = col >> 2, pp = (col >> 1) & 1, ro = col & 1;
    const float* yv = y + ((size_t)b * MDIM + m) * 8;
    float re, im;
    pauli_entry(yv, p, pp, &re, &im);
    g_yr[idx] = ro ? im : re;
}

__global__ void init_all() {
    int idx = blockIdx.x * blockDim.x + threadIdx.x;
    if (idx < BDIM * NDIM * 8) g_xs[idx] = 0.0f;
    if (idx < 128 * KRF) g_X[idx] = __float2half(0.0f);
    if (idx < 8 * 32) g_sub[idx] = 0u;
    if (idx == 0) g_root = 0u;
}

// ---------------- fwd gemm phase (unchanged from R8) ----------------
__device__ __forceinline__ void issue_stage_f(
    uint32_t sb, int buf, int tid, int c0, int kk)
{
    uint32_t base = sb + buf * BUF_BYTES;
#pragma unroll
    for (int r = 0; r < 3; r++) {
        int q = tid + (r << 9);                // 1536 16B chunks per stage
        const __half* gp;
        uint32_t tb;
        int row, cc;
        if (q < 1024) {                        // A = X: 128 rows x 8 chunks
            row = q >> 3; cc = q & 7;
            gp = g_X + (size_t)row * KRF + kk + cc * 8;
            tb = base;
        } else {                               // B = Wf tile: 64 rows x 8 chunks
            int q2 = q - 1024;
            row = q2 >> 3; cc = q2 & 7;
            gp = g_Wf + (size_t)(c0 + row) * KRF + kk + cc * 8;
            tb = base + 16384;
        }
        uint32_t off = (uint32_t)((row << 7) | ((cc ^ (row & 7)) << 4));
        CP_ASYNC16(tb + off, gp);
    }
    CP_COMMIT();
}

__device__ void fwd_gemm(uint32_t sb, int c0, int ks) {
    const int tid = threadIdx.x;
    const int k0 = ks * 256;
    const int nst = 4;

    const int warp = tid >> 5, lane = tid & 31;
    const int wm = warp >> 2;
    const int wn = warp & 3;
    const int lrow = lane & 15;
    const int lhalf = lane >> 4;
    const int lsw = lrow & 7;

    float acc[2][2][4];
#pragma unroll
    for (int am = 0; am < 2; am++)
#pragma unroll
        for (int sel = 0; sel < 2; sel++)
#pragma unroll
            for (int v = 0; v < 4; v++) acc[am][sel][v] = 0.0f;

    issue_stage_f(sb, 0, tid, c0, k0);

    for (int s = 0; s < nst; s++) {
        if (s + 1 < nst) {
            issue_stage_f(sb, (s + 1) & 1, tid, c0, k0 + (s + 1) * KT);
            CP_WAIT1();
        } else {
            CP_COMMIT();
            CP_WAIT0();
        }
        __syncthreads();

        uint32_t bufb = sb + (s & 1) * BUF_BYTES;
#pragma unroll
        for (int kk = 0; kk < 4; kk++) {
            uint32_t ksel = (uint32_t)((((kk << 1) | lhalf) ^ lsw) << 4);
            uint32_t ah[2][4], bb[4];
#pragma unroll
            for (int am = 0; am < 2; am++) {
                uint32_t rb = (uint32_t)((wm * 32 + am * 16 + lrow) << 7) + ksel;
                ldsm4(ah[am], bufb + rb);
            }
            {
                uint32_t rb = (uint32_t)((wn * 16 + lrow) << 7) + ksel;
                ldsm4(bb, bufb + 16384u + rb);
            }
#pragma unroll
            for (int am = 0; am < 2; am++)
#pragma unroll
                for (int sel = 0; sel < 2; sel++)
                    mma_fp16(acc[am][sel], ah[am], bb[sel], bb[sel + 2]);
        }
        __syncthreads();
    }

    const int qrow = lane >> 2, qcol2 = (lane & 3) << 1;
    float* po = g_pf + (size_t)ks * 128 * CCF;
#pragma unroll
    for (int am = 0; am < 2; am++)
#pragma unroll
        for (int sel = 0; sel < 2; sel++) {
            int row = wm * 32 + am * 16 + qrow;
            int col = c0 + wn * 16 + sel * 8 + qcol2;
            *reinterpret_cast<float2*>(&po[(size_t)row * CCF + col]) =
                make_float2(acc[am][sel][0], acc[am][sel][1]);
            *reinterpret_cast<float2*>(&po[(size_t)(row + 8) * CCF + col]) =
                make_float2(acc[am][sel][2], acc[am][sel][3]);
        }
}

// ---------------- bwd gemm, full-K, fused upd/shrink epilogue ----------------
// CTA: 16 out cols (c0 = cta*16), K = 1024 full, 16 stages of KT=64.
// Warp tile m16 x n8: wm = warp&7 (rows wm*16), wn = warp>>3 (cols c0+wn*8).
__device__ __forceinline__ void issue_stage_b(
    uint32_t sb, int buf, int tid, int c0, int kk)
{
    uint32_t base = sb + buf * BUF_BYTES;
#pragma unroll
    for (int r = 0; r < 3; r++) {
        int q = tid + (r << 9);                // 1152 chunks: A 1024 | B 128
        if (q < 1152) {
            const __half* gp;
            uint32_t tb;
            int row, cc;
            if (q < 1024) {                    // A = E: 128 rows x 8 chunks
                row = q >> 3; cc = q & 7;
                gp = g_E + (size_t)row * KRB + kk + cc * 8;
                tb = base;
            } else {                           // B = Wb tile: 16 rows x 8 chunks
                int q2 = q - 1024;
                row = q2 >> 3; cc = q2 & 7;
                gp = g_Wb + (size_t)(c0 + row) * KRB + kk + cc * 8;
                tb = base + 16384;
            }
            uint32_t off = (uint32_t)((row << 7) | ((cc ^ (row & 7)) << 4));
            CP_ASYNC16(tb + off, gp);
        }
    }
    CP_COMMIT();
}

__device__ void bwd_fused(uint32_t sb, char* smemp, int cta) {
    const int tid = threadIdx.x;
    const int warp = tid >> 5, lane = tid & 31;
    const int wm = warp & 7;                   // rows wm*16..+15
    const int wn = warp >> 3;                  // cols c0 + wn*8
    const int c0 = cta * 16;
    const int lrow = lane & 15;
    const int lhalf = lane >> 4;
    const int lsw = lrow & 7;

    float acc[4] = {0.f, 0.f, 0.f, 0.f};

    issue_stage_b(sb, 0, tid, c0, 0);

    for (int s = 0; s < 16; s++) {
        if (s + 1 < 16) {
            issue_stage_b(sb, (s + 1) & 1, tid, c0, (s + 1) * KT);
            CP_WAIT1();
        } else {
            CP_COMMIT();
            CP_WAIT0();
        }
        __syncthreads();

        uint32_t bufb = sb + (s & 1) * BUF_BYTES;
#pragma unroll
        for (int kk2 = 0; kk2 < 2; kk2++) {    // two k32 halves of the stage
            uint32_t a0[4], a1[4], bb[4];
            {
                uint32_t rb = (uint32_t)((wm * 16 + lrow) << 7);
                int kk = kk2 * 2;
                uint32_t ks0 = (uint32_t)((((kk << 1) | lhalf) ^ lsw) << 4);
                uint32_t ks1 = (uint32_t)(((((kk + 1) << 1) | lhalf) ^ lsw) << 4);
                ldsm4(a0, bufb + rb + ks0);
                ldsm4(a1, bufb + rb + ks1);
            }
            {
                // B n8 x k32: 4 8x8 k-slabs; lane group (lane>>3) picks slab
                int brow = wn * 8 + (lane & 7);
                int cc = kk2 * 4 + (lane >> 3);
                uint32_t off = (uint32_t)((brow << 7) | ((cc ^ (brow & 7)) << 4));
                ldsm4(bb, bufb + 16384u + off);
            }
            mma_fp16(acc, a0, bb[0], bb[1]);
            mma_fp16(acc, a1, bb[2], bb[3]);
        }
        __syncthreads();
    }

    // ---- fused epilogue: warp-local 16x8 tile -> blade butterfly -> shrink ----
    float* wt = reinterpret_cast<float*>(smemp) + warp * 128;   // 16x8 fp32
    {
        int r = lane >> 2, c2 = (lane & 3) << 1;
        wt[r * 8 + c2] = acc[0];
        wt[r * 8 + c2 + 1] = acc[1];
        wt[(r + 8) * 8 + c2] = acc[2];
        wt[(r + 8) * 8 + c2 + 1] = acc[3];
    }
    __syncwarp();
    if (lane < 16) {
        int bl = lane >> 1, nl = lane & 1;
        int b = wm * 8 + bl;
        int n = cta * 4 + wn * 2 + nl;
        float G0[4], G1[4];
#pragma unroll
        for (int i = 0; i < 4; i++) {
            G0[i] = wt[(2 * bl) * 8 + 4 * nl + i];
            G1[i] = wt[(2 * bl + 1) * 8 + 4 * nl + i];
        }
        float g[8];
        g[0] = 0.5f * (G0[0] + G1[2]);
        g[4] = 0.5f * (G0[0] - G1[2]);
        g[3] = 0.5f * (G0[1] - G1[3]);
        g[7] = 0.5f * (G0[1] + G1[3]);
        g[1] = 0.5f * (G0[2] + G1[0]);
        g[5] = 0.5f * (G1[0] - G0[2]);
        g[2] = 0.5f * (G1[1] - G0[3]);
        g[6] = 0.5f * (G0[3] + G1[1]);

        int idx = b * NDIM + n;
        float* xs = g_xs + (size_t)idx * 8;
        float x[8];
#pragma unroll
        for (int i = 0; i < 8; i++) {
            float xv = xs[i] - STEPF * g[i];
            float thr = (i == 0) ? 0.0f : ((i == 7) ? 0.002f : 0.001f);
            float a = fabsf(xv) - thr;
            x[i] = (a > 0.0f) ? copysignf(a, xv) : 0.0f;
            xs[i] = x[i];
        }
        __half2* X0 = reinterpret_cast<__half2*>(&g_X[(size_t)(2 * b) * KRF + 4 * n]);
        __half2* X1 = reinterpret_cast<__half2*>(&g_X[(size_t)(2 * b + 1) * KRF + 4 * n]);
        X0[0] = __floats2half2_rn(x[0] + x[4], x[3] + x[7]);
        X0[1] = __floats2half2_rn(x[1] - x[5], -x[2] + x[6]);
        X1[0] = __floats2half2_rn(x[1] + x[5], x[2] + x[6]);
        X1[1] = __floats2half2_rn(x[0] - x[4], -x[3] + x[7]);
    }
}

// ---------------- persistent kernel ----------------
__global__ __launch_bounds__(NTHREADS, 1) void ista_persist(float* __restrict__ out) {
    extern __shared__ char smem[];
    uint32_t sb = smem_u32(smem);
    const int cta = blockIdx.x;
    const int t = threadIdx.x;
    unsigned nb = 0;

    for (int it = 0; it < NITER; it++) {
        // ---- fwd: pf[ks] = X(128x2048) @ Wf-tile ----
        fwd_gemm(sb, (cta & 15) * 64, cta >> 4);
        grid_bar(++nb, cta);

        // ---- err: E = sum(pf) - yr, fp16 (coalesced) ----
#pragma unroll
        for (int i = 0; i < 2; i++) {
            int idx = cta * NTHREADS + t + i * (GRID * NTHREADS);
            float s = 0.0f;
#pragma unroll
            for (int p = 0; p < FWD_SPLIT; p++)
                s += g_pf[(size_t)p * 128 * CCF + idx];
            g_E[idx] = __float2half(s - g_yr[idx]);
        }
        grid_bar(++nb, cta);

        // ---- bwd full-K + fused upd/shrink/blade->matrix ----
        bwd_fused(sb, smem, cta);
        grid_bar(++nb, cta);
    }

    // ---- out = blade state (already output layout) ----
    {
        int idx = cta * NTHREADS + t;
        reinterpret_cast<float4*>(out)[idx] =
            reinterpret_cast<const float4*>(g_xs)[idx];
    }
}

// ---------------- host ----------------
extern "C" void kernel_launch(void* const* d_in, const int* in_sizes, int n_in,
                              void* d_out, int out_size)
{
    const float* y = (const float*)d_in[0];
    const float* A = (const float*)d_in[1];
    if (n_in >= 2 && in_sizes[0] > in_sizes[1]) {
        const float* t = y; y = A; A = t;
    }

    cudaFuncSetAttribute(ista_persist, cudaFuncAttributeMaxDynamicSharedMemorySize, SMEM_TOTAL);

    build_wf<<<(int)(((size_t)CCF * KRF + 255) / 256), 256>>>(A);
    build_wb<<<(int)(((size_t)CCB * KRB + 255) / 256), 256>>>(A);
    build_yr<<<(128 * CCF + 255) / 256, 256>>>(y);
    init_all<<<(128 * KRF + 255) / 256, 256>>>();

    ista_persist<<<GRID, NTHREADS, SMEM_TOTAL>>>((float*)d_out);
}

// round 12
// speedup vs baseline: 1.3976x; 1.1101x over previous
#include <cuda_runtime.h>
#include <cuda_fp16.h>
#include <cstdint>

// CliffordISTA — Round 11: Pauli/M2(C) fp16 GEMMs (R8 gemm, unchanged) with ALL
// global grid barriers replaced by per-tile dataflow flags (monotonic counters).
// Double-buffered pf/pb/E/X by iteration parity; no final barrier (upd CTAs
// write their own output chunks at the last iteration).

#define NDIM 512
#define MDIM 256
#define BDIM 64
#define NITER 50
#define STEPF 0.01f
#define KT 64
#define NTHREADS 512
#define GRID 128
#define FWD_SPLIT 8
#define BWD_SPLIT 4
#define KRF 2048   // fwd realified K  (4*NDIM)
#define CCF 1024   // fwd out cols     (4*MDIM)
#define KRB 1024   // bwd realified K
#define CCB 2048   // bwd out cols

#define BUF_BYTES 24576          // per stage: A-op 16K | B-op 8K
#define SMEM_TOTAL (2 * BUF_BYTES)

// ---------------- device globals ----------------
__device__ __half g_Wf[(size_t)CCF * KRF];     // [col][k] 4MB
__device__ __half g_Wb[(size_t)CCB * KRB];     // [col][k] 4MB
__device__ __half g_X[2][128 * KRF];           // realified x, parity buffered
__device__ __half g_E[2][128 * KRB];           // realified err
__device__ float g_xs[BDIM * NDIM * 8];        // blade state (CTA-private chunks)
__device__ float g_yr[128 * CCF];              // realified y
__device__ float g_pf[2][(size_t)FWD_SPLIT * 128 * CCF];   // 2 x 4MB
__device__ float g_pb[2][(size_t)BWD_SPLIT * 128 * CCB];   // 2 x 4MB
// dataflow flags: one 128B line each
__device__ unsigned g_ff[16 * 32];             // fwd done per fwd-coltile (8/iter)
__device__ unsigned g_fe[16 * 32];             // err done per err-coltile (8/iter)
__device__ unsigned g_fb[32 * 32];             // bwd done per bwd-coltile (4/iter)
__device__ unsigned g_fu[32 * 32];             // upd done per upd-coltile (4/iter)

// ---------------- helpers ----------------
__device__ __forceinline__ uint32_t smem_u32(const void* p) {
    uint32_t a;
    asm("{ .reg .u64 t; cvta.to.shared.u64 t, %1; cvt.u32.u64 %0, t; }" : "=r"(a) : "l"(p));
    return a;
}

#define CP_ASYNC16(smem, gptr) \
    asm volatile("cp.async.cg.shared.global [%0], [%1], 16;" :: "r"(smem), "l"(gptr))
#define CP_COMMIT() asm volatile("cp.async.commit_group;" ::: "memory")
#define CP_WAIT1()  asm volatile("cp.async.wait_group 1;" ::: "memory")
#define CP_WAIT0()  asm volatile("cp.async.wait_group 0;" ::: "memory")

__device__ __forceinline__ void ldsm4(uint32_t* r, uint32_t addr) {
    asm volatile("ldmatrix.sync.aligned.m8n8.x4.shared.b16 {%0,%1,%2,%3}, [%4];"
                 : "=r"(r[0]), "=r"(r[1]), "=r"(r[2]), "=r"(r[3]) : "r"(addr));
}

__device__ __forceinline__ void mma_fp16(float* c, const uint32_t* a, uint32_t b0, uint32_t b1) {
    asm volatile(
        "mma.sync.aligned.m16n8k16.row.col.f32.f16.f16.f32 "
        "{%0,%1,%2,%3}, {%4,%5,%6,%7}, {%8,%9}, {%0,%1,%2,%3};"
        : "+f"(c[0]), "+f"(c[1]), "+f"(c[2]), "+f"(c[3])
        : "r"(a[0]), "r"(a[1]), "r"(a[2]), "r"(a[3]), "r"(b0), "r"(b1));
}

// M(v)[q][p] for blade vector v[8]  (blades [1,e1,e2,e12,e3,e13,e23,e123])
__device__ __forceinline__ void pauli_entry(const float* v, int q, int p,
                                            float* re, float* im) {
    if (q == 0) {
        if (p == 0) { *re = v[0] + v[4]; *im = v[3] + v[7]; }
        else        { *re = v[1] - v[5]; *im = -v[2] + v[6]; }
    } else {
        if (p == 0) { *re = v[1] + v[5]; *im = v[2] + v[6]; }
        else        { *re = v[0] - v[4]; *im = -v[3] + v[7]; }
    }
}

__device__ __forceinline__ void flag_wait(const unsigned* f, unsigned tgt) {
    unsigned v;
    do {
        asm volatile("ld.volatile.global.u32 %0, [%1];" : "=r"(v) : "l"(f));
    } while ((int)(v - tgt) < 0);
}

// ---------------- build / init ----------------
__global__ void build_wf(const float* __restrict__ A) {
    size_t idx = (size_t)blockIdx.x * blockDim.x + threadIdx.x;
    if (idx >= (size_t)CCF * KRF) return;
    int col = (int)(idx >> 11), k = (int)(idx & (KRF - 1));
    int m = col >> 2, pp = (col >> 1) & 1, ro = col & 1;
    int n = k >> 2, q = (k >> 1) & 1, ri = k & 1;
    const float* a = A + ((size_t)m * NDIM + n) * 8;
    float re, im;
    pauli_entry(a, q, pp, &re, &im);
    float v = (ri == 0) ? (ro == 0 ? re : im) : (ro == 0 ? -im : re);
    g_Wf[idx] = __float2half(v);
}

__global__ void build_wb(const float* __restrict__ A) {
    size_t idx = (size_t)blockIdx.x * blockDim.x + threadIdx.x;
    if (idx >= (size_t)CCB * KRB) return;
    int col = (int)(idx >> 10), k = (int)(idx & (KRB - 1));
    int n = col >> 2, qp = (col >> 1) & 1, ro = col & 1;
    int m = k >> 2, p = (k >> 1) & 1, ri = k & 1;
    const float* a = A + ((size_t)m * NDIM + n) * 8;
    float re, im;
    pauli_entry(a, qp, p, &re, &im);       // conj applied via signs below
    float v = (ri == 0) ? (ro == 0 ? re : -im) : (ro == 0 ? im : re);
    g_Wb[idx] = __float2half(v);
}

__global__ void build_yr(const float* __restrict__ y) {
    int idx = blockIdx.x * blockDim.x + threadIdx.x;
    if (idx >= 128 * CCF) return;
    int row = idx >> 10, col = idx & (CCF - 1);
    int b = row >> 1, p = row & 1;
    int m = col >> 2, pp = (col >> 1) & 1, ro = col & 1;
    const float* yv = y + ((size_t)b * MDIM + m) * 8;
    float re, im;
    pauli_entry(yv, p, pp, &re, &im);
    g_yr[idx] = ro ? im : re;
}

__global__ void init_all() {
    int idx = blockIdx.x * blockDim.x + threadIdx.x;
    if (idx < BDIM * NDIM * 8) g_xs[idx] = 0.0f;
    if (idx < 128 * KRF) {
        g_X[0][idx] = __float2half(0.0f);
        g_X[1][idx] = __float2half(0.0f);
    }
    if (idx < 16 * 32) { g_ff[idx] = 0u; g_fe[idx] = 0u; }
    if (idx < 32 * 32) { g_fb[idx] = 0u; g_fu[idx] = 0u; }
}

// ---------------- gemm (R8, unchanged) ----------------
__device__ __forceinline__ void issue_stage(
    uint32_t sb, int buf, int tid, const __half* Xm, const __half* Wm,
    int Kdim, int c0, int kk)
{
    uint32_t base = sb + buf * BUF_BYTES;
#pragma unroll
    for (int r = 0; r < 3; r++) {
        int q = tid + (r << 9);                // 1536 16B chunks per stage
        const __half* gp;
        uint32_t tb;
        int row, cc;
        if (q < 1024) {                        // A: 128 rows x 8 chunks
            row = q >> 3; cc = q & 7;
            gp = Xm + (size_t)row * Kdim + kk + cc * 8;
            tb = base;
        } else {                               // B: 64 rows x 8 chunks
            int q2 = q - 1024;
            row = q2 >> 3; cc = q2 & 7;
            gp = Wm + (size_t)(c0 + row) * Kdim + kk + cc * 8;
            tb = base + 16384;
        }
        uint32_t off = (uint32_t)((row << 7) | ((cc ^ (row & 7)) << 4));
        CP_ASYNC16(tb + off, gp);
    }
    CP_COMMIT();
}

__device__ void gemm_phase(uint32_t sb, const __half* Xm, const __half* Wm,
                           float* part, int Kdim, int Cc, int c0, int ks)
{
    const int tid = threadIdx.x;
    const int k0 = ks * 256;
    const int nst = 4;

    const int warp = tid >> 5, lane = tid & 31;
    const int wm = warp >> 2;
    const int wn = warp & 3;
    const int lrow = lane & 15;
    const int lhalf = lane >> 4;
    const int lsw = lrow & 7;

    float acc[2][2][4];
#pragma unroll
    for (int am = 0; am < 2; am++)
#pragma unroll
        for (int sel = 0; sel < 2; sel++)
#pragma unroll
            for (int v = 0; v < 4; v++) acc[am][sel][v] = 0.0f;

    issue_stage(sb, 0, tid, Xm, Wm, Kdim, c0, k0);

    for (int s = 0; s < nst; s++) {
        if (s + 1 < nst) {
            issue_stage(sb, (s + 1) & 1, tid, Xm, Wm, Kdim, c0, k0 + (s + 1) * KT);
            CP_WAIT1();
        } else {
            CP_COMMIT();
            CP_WAIT0();
        }
        __syncthreads();

        uint32_t bufb = sb + (s & 1) * BUF_BYTES;
#pragma unroll
        for (int kk = 0; kk < 4; kk++) {
            uint32_t ksel = (uint32_t)((((kk << 1) | lhalf) ^ lsw) << 4);
            uint32_t ah[2][4], bb[4];
#pragma unroll
            for (int am = 0; am < 2; am++) {
                uint32_t rb = (uint32_t)((wm * 32 + am * 16 + lrow) << 7) + ksel;
                ldsm4(ah[am], bufb + rb);
            }
            {
                uint32_t rb = (uint32_t)((wn * 16 + lrow) << 7) + ksel;
                ldsm4(bb, bufb + 16384u + rb);
            }
#pragma unroll
            for (int am = 0; am < 2; am++)
#pragma unroll
                for (int sel = 0; sel < 2; sel++)
                    mma_fp16(acc[am][sel], ah[am], bb[sel], bb[sel + 2]);
        }
        __syncthreads();
    }

    const int qrow = lane >> 2, qcol2 = (lane & 3) << 1;
    float* po = part + (size_t)ks * 128 * Cc;
#pragma unroll
    for (int am = 0; am < 2; am++)
#pragma unroll
        for (int sel = 0; sel < 2; sel++) {
            int row = wm * 32 + am * 16 + qrow;
            int col = c0 + wn * 16 + sel * 8 + qcol2;
            *reinterpret_cast<float2*>(&po[(size_t)row * Cc + col]) =
                make_float2(acc[am][sel][0], acc[am][sel][1]);
            *reinterpret_cast<float2*>(&po[(size_t)(row + 8) * Cc + col]) =
                make_float2(acc[am][sel][2], acc[am][sel][3]);
        }
}

// ---------------- persistent kernel (dataflow) ----------------
__global__ __launch_bounds__(NTHREADS, 1) void ista_persist(float* __restrict__ out) {
    extern __shared__ char smem[];
    uint32_t sb = smem_u32(smem);
    const int cta = blockIdx.x;
    const int t = threadIdx.x;

    const int ct = cta & 15;       // fwd/err coltile (16)
    const int ks = cta >> 4;       // fwd split / err sub (8)
    const int ct2 = cta >> 2;      // bwd/upd coltile (32)
    const int ks2 = cta & 3;       // bwd split / upd sub (4)

    for (int it = 0; it < NITER; it++) {
        const int p = it & 1;

        // ---- fwd: pf[p][ks] cols [ct*64,+64) = X[p] @ Wf-tile ----
        // (wait for X[p] producers was done at end of previous iteration)
        gemm_phase(sb, g_X[p], g_Wf, g_pf[p], KRF, CCF, ct * 64, ks);
        __syncthreads();
        if (t == 0) {
            __threadfence();
            atomicAdd(&g_ff[ct * 32], 1u);
            flag_wait(&g_ff[ct * 32], 8u * (it + 1));   // all 8 splits of my tile
            __threadfence();
        }
        __syncthreads();

        // ---- err chunk: rows [ks*16,+16), cols [ct*64,+64) ----
        {
            int row = ks * 16 + (t >> 5);
            int col = ct * 64 + (t & 31) * 2;
            float2 s = make_float2(0.f, 0.f);
#pragma unroll
            for (int q = 0; q < FWD_SPLIT; q++) {
                float2 v = *reinterpret_cast<const float2*>(
                    &g_pf[p][(size_t)q * 128 * CCF + (size_t)row * CCF + col]);
                s.x += v.x; s.y += v.y;
            }
            float2 yv = *reinterpret_cast<const float2*>(&g_yr[(size_t)row * CCF + col]);
            *reinterpret_cast<__half2*>(&g_E[p][(size_t)row * KRB + col]) =
                __floats2half2_rn(s.x - yv.x, s.y - yv.y);
        }
        __syncthreads();
        if (t == 0) {
            __threadfence();
            atomicAdd(&g_fe[ct * 32], 1u);
            // bwd needs err coltiles [ks2*4 .. ks2*4+3]
#pragma unroll
            for (int j = 0; j < 4; j++)
                flag_wait(&g_fe[(ks2 * 4 + j) * 32], 8u * (it + 1));
            __threadfence();
        }
        __syncthreads();

        // ---- bwd: pb[p][ks2] cols [ct2*64,+64) = E[p] @ Wb-tile ----
        gemm_phase(sb, g_E[p], g_Wb, g_pb[p], KRB, CCB, ct2 * 64, ks2);
        __syncthreads();
        if (t == 0) {
            __threadfence();
            atomicAdd(&g_fb[ct2 * 32], 1u);
            flag_wait(&g_fb[ct2 * 32], 4u * (it + 1));  // all 4 splits of my tile
            __threadfence();
        }
        __syncthreads();

        // ---- upd chunk: b in [ks2*16,+16), n in [ct2*16,+16) ----
        if (t < 256) {
            int b = ks2 * 16 + (t >> 4);
            int n = ct2 * 16 + (t & 15);
            size_t r0 = (size_t)(2 * b) * CCB + 4 * n;
            size_t r1 = r0 + CCB;
            float4 G0 = make_float4(0.f, 0.f, 0.f, 0.f);
            float4 G1 = make_float4(0.f, 0.f, 0.f, 0.f);
#pragma unroll
            for (int q = 0; q < BWD_SPLIT; q++) {
                float4 a = *reinterpret_cast<const float4*>(
                    &g_pb[p][(size_t)q * 128 * CCB + r0]);
                float4 c = *reinterpret_cast<const float4*>(
                    &g_pb[p][(size_t)q * 128 * CCB + r1]);
                G0.x += a.x; G0.y += a.y; G0.z += a.z; G0.w += a.w;
                G1.x += c.x; G1.y += c.y; G1.z += c.z; G1.w += c.w;
            }
            float g[8];
            g[0] = 0.5f * (G0.x + G1.z);
            g[4] = 0.5f * (G0.x - G1.z);
            g[3] = 0.5f * (G0.y - G1.w);
            g[7] = 0.5f * (G0.y + G1.w);
            g[1] = 0.5f * (G0.z + G1.x);
            g[5] = 0.5f * (G1.x - G0.z);
            g[2] = 0.5f * (G1.y - G0.w);
            g[6] = 0.5f * (G0.w + G1.y);

            int idx = b * NDIM + n;
            float* xs = g_xs + (size_t)idx * 8;
            float x[8];
#pragma unroll
            for (int i = 0; i < 8; i++) {
                float xv = xs[i] - STEPF * g[i];
                float thr = (i == 0) ? 0.0f : ((i == 7) ? 0.002f : 0.001f);
                float a = fabsf(xv) - thr;
                x[i] = (a > 0.0f) ? copysignf(a, xv) : 0.0f;
                xs[i] = x[i];
            }
            const int p1 = (it + 1) & 1;
            __half2* X0 = reinterpret_cast<__half2*>(&g_X[p1][(size_t)(2 * b) * KRF + 4 * n]);
            __half2* X1 = reinterpret_cast<__half2*>(&g_X[p1][(size_t)(2 * b + 1) * KRF + 4 * n]);
            X0[0] = __floats2half2_rn(x[0] + x[4], x[3] + x[7]);
            X0[1] = __floats2half2_rn(x[1] - x[5], -x[2] + x[6]);
            X1[0] = __floats2half2_rn(x[1] + x[5], x[2] + x[6]);
            X1[1] = __floats2half2_rn(x[0] - x[4], -x[3] + x[7]);

            if (it == NITER - 1) {
                float4* po = reinterpret_cast<float4*>(&out[(size_t)idx * 8]);
                po[0] = make_float4(x[0], x[1], x[2], x[3]);
                po[1] = make_float4(x[4], x[5], x[6], x[7]);
            }
        }
        __syncthreads();
        if (t == 0) {
            __threadfence();
            atomicAdd(&g_fu[ct2 * 32], 1u);
            if (it + 1 < NITER) {
                // next fwd needs upd coltiles [ks*4 .. ks*4+3]
#pragma unroll
                for (int j = 0; j < 4; j++)
                    flag_wait(&g_fu[(ks * 4 + j) * 32], 4u * (it + 1));
                __threadfence();
            }
        }
        __syncthreads();
    }
}

// ---------------- host ----------------
extern "C" void kernel_launch(void* const* d_in, const int* in_sizes, int n_in,
                              void* d_out, int out_size)
{
    const float* y = (const float*)d_in[0];
    const float* A = (const float*)d_in[1];
    if (n_in >= 2 && in_sizes[0] > in_sizes[1]) {
        const float* t = y; y = A; A = t;
    }

    cudaFuncSetAttribute(ista_persist, cudaFuncAttributeMaxDynamicSharedMemorySize, SMEM_TOTAL);

    build_wf<<<(int)(((size_t)CCF * KRF + 255) / 256), 256>>>(A);
    build_wb<<<(int)(((size_t)CCB * KRB + 255) / 256), 256>>>(A);
    build_yr<<<(128 * CCF + 255) / 256, 256>>>(y);
    init_all<<<(128 * KRF + 255) / 256, 256>>>();

    ista_persist<<<GRID, NTHREADS, SMEM_TOTAL>>>((float*)d_out);
}